// round 12
// baseline (speedup 1.0000x reference)
#include <cuda_runtime.h>

#define Bn   8
#define Tn   64
#define NIn  256
#define Nn   512
#define NOn  32
#define Dn   4
#define NBLK 128
#define NTHR 512
#define OB   32

// ---------------- global scratch (static __device__, allocation-free) --------
__device__ float          g_inp[Bn * Tn * Nn];        // input projection (b,t,n)
__device__ float2         g_rec[Tn * Bn * Nn];        // {synp, bf16(xb)|spikebit}
__device__ float2         g_pk[(size_t)Nn * Nn];      // per-(o,e): {wv, bf16x2(A_p,A_d)}
__device__ unsigned char  g_di[(size_t)Nn * Nn];      // per-(o,e): delay bin
__device__ float          g_h2p[NBLK * Tn * NOn];     // per-CTA readout partials
__device__ unsigned       g_bar[Bn * 32];             // per-batch barrier counters

// ---------------- K0: reset barriers, zero ring, build packed matrix ---------
__global__ void k_pack(const float* __restrict__ w,
                       const float* __restrict__ wsg,
                       const float* __restrict__ Ap,
                       const float* __restrict__ Ad,
                       const float* __restrict__ dmap) {
    if (blockIdx.x == 0 && threadIdx.x < Bn * 32) g_bar[threadIdx.x] = 0u;

    // zero the recording ring (replay determinism + (t-d)<0 wrap reads)
    {
        const int nf4 = Tn * Bn * Nn / 2;          // float4 count (float2 ring)
        float4 z = make_float4(0.f, 0.f, 0.f, 0.f);
        for (int i = blockIdx.x * blockDim.x + threadIdx.x; i < nf4;
             i += gridDim.x * blockDim.x)
            ((float4*)g_rec)[i] = z;
    }

    // 32x32 tile transpose: read (e,o)-major coalesced, write (o,e)-major coalesced
    __shared__ float         swv[32][33];
    __shared__ unsigned      sa[32][33];
    __shared__ unsigned char sdi[32][33];

    int tx = threadIdx.x & 31, ty = threadIdx.x >> 5;     // 32 x 8
    int te = (blockIdx.x & 15) << 5;
    int to = (blockIdx.x >> 4) << 5;

    for (int j = 0; j < 4; j++) {
        int e = te + ty + 8 * j, o = to + tx;
        size_t eo = (size_t)e * Nn + o;
        float wv = wsg[e] * fabsf(w[eo]);
        unsigned ua = __float_as_uint(Ap[eo]);
        unsigned ub = __float_as_uint(Ad[eo]);
        unsigned ap = (ua + 0x7FFFu + ((ua >> 16) & 1u)) >> 16;   // bf16 rne
        unsigned ad = (ub + 0x7FFFu + ((ub >> 16) & 1u)) >> 16;
        int d = 0;
        for (int dd = 0; dd < Dn; dd++)
            if (dmap[((size_t)dd * Nn + e) * Nn + o] > 0.5f) d = dd;
        swv[ty + 8 * j][tx] = wv;
        sa[ty + 8 * j][tx]  = ap | (ad << 16);
        sdi[ty + 8 * j][tx] = (unsigned char)d;
    }
    __syncthreads();
    for (int j = 0; j < 4; j++) {
        int o = to + ty + 8 * j, e = te + tx;
        g_pk[(size_t)o * Nn + e] =
            make_float2(swv[tx][ty + 8 * j], __uint_as_float(sa[tx][ty + 8 * j]));
        g_di[(size_t)o * Nn + e] = sdi[tx][ty + 8 * j];
    }
}

// ---------------- K_in: inp = einsum('btc,cn->btn', inputs, w_in) ------------
__global__ void k_inp(const float* __restrict__ x, const float* __restrict__ win) {
    __shared__ float xs[8][NIn];
    int bt0 = blockIdx.x * 8;
    int tid = threadIdx.x;                    // 256
    for (int i = tid; i < 8 * NIn; i += 256) {
        int r = i >> 8, c = i & 255;
        xs[r][c] = x[(size_t)(bt0 + r) * NIn + c];
    }
    __syncthreads();
    for (int half = 0; half < 2; half++) {
        int n = tid + half * 256;
        float acc[8] = {0.f, 0.f, 0.f, 0.f, 0.f, 0.f, 0.f, 0.f};
        for (int c = 0; c < NIn; c++) {
            float wv = win[(size_t)c * Nn + n];
#pragma unroll
            for (int r = 0; r < 8; r++) acc[r] = fmaf(xs[r][c], wv, acc[r]);
        }
#pragma unroll
        for (int r = 0; r < 8; r++) g_inp[(size_t)(bt0 + r) * Nn + n] = acc[r];
    }
}

// ---------------- K1: persistent stepping kernel -----------------------------
// CTA = (batch b, 32 output neurons). Synapse matrix in REGISTERS (persistent,
// 1 CTA/SM); w_stdp slab in smem; grid barrier per batch (16 CTAs).
__global__ void __launch_bounds__(NTHR, 1)
k_step(const int* __restrict__ delays, const float* __restrict__ p,
       const float* __restrict__ wout) {
    extern __shared__ char smem[];
    float*  ws    = (float*)smem;                                  // [OB][Nn] 64KB
    float2* gbuf  = (float2*)(smem + OB * Nn * 4);                 // [Dn][Nn] 16KB
    float*  wouts = (float*)(smem + OB * Nn * 4 + Dn * Nn * 8);    // [32][32] 4KB
    float*  aux   = wouts + 32 * 32;
    float* mem_s = aux +   0;  float* wp_s  = aux +  32;
    float* xb_s  = aux +  64;  float* up_s  = aux +  96;
    float* ud_s  = aux + 128;  float* potg  = aux + 160;
    float* depg  = aux + 192;  float* syn_s = aux + 224;
    float* p_s   = aux + 256;  float* pd_s  = aux + 288;
    float* spks  = aux + 320;
    int*   dly   = (int*)(aux + 352);

    const int tid = threadIdx.x;
    const int cta = blockIdx.x;
    const int b   = cta >> 4;
    const int o0  = (cta & 15) << 5;
    const int lane = tid & 31, wrp = tid >> 5;

    // ---- one-time: load this thread's 32 synapses into registers ----
    float    wvr[32];
    unsigned aar[32];
    unsigned dp0 = 0u, dp1 = 0u;
#pragma unroll
    for (int i = 0; i < 16; i++) {
        int e = lane + (i << 5);
        size_t r0 = (size_t)(o0 + wrp * 2 + 0) * Nn + e;
        size_t r1 = (size_t)(o0 + wrp * 2 + 1) * Nn + e;
        float2 m0 = __ldg(&g_pk[r0]);
        float2 m1 = __ldg(&g_pk[r1]);
        wvr[i]      = m0.x;  aar[i]      = __float_as_uint(m0.y);
        wvr[16 + i] = m1.x;  aar[16 + i] = __float_as_uint(m1.y);
        dp0 |= ((unsigned)__ldg(&g_di[r0]) & 3u) << (2 * i);
        dp1 |= ((unsigned)__ldg(&g_di[r1]) & 3u) << (2 * i);
    }

    for (int i = tid; i < OB * Nn; i += NTHR) ws[i] = 1.0f;
    for (int i = tid; i < 32 * 32; i += NTHR)
        wouts[i] = wout[(size_t)(o0 + (i >> 5)) * NOn + (i & 31)];
    if (tid < 32) {
        mem_s[tid] = 0.f; wp_s[tid] = 0.f; xb_s[tid] = 0.f;
        up_s[tid] = 0.f;  ud_s[tid] = 0.f;
        float pv = p[o0 + tid];
        p_s[tid] = pv; pd_s[tid] = (pv < 0.f) ? 1.f : 0.f;
    }
    if (tid < 4) dly[tid] = delays[tid];
    __syncthreads();
    const int d0 = dly[0], d1 = dly[1], d2 = dly[2], d3 = dly[3];

    volatile unsigned* vb = &g_bar[b * 32];
    float memv = 0.f, spk = 0.f;

    for (int t = 0; t < Tn; t++) {
        // ---- Phase A: spikes, recording, fast state (pre-update semantics) ----
        if (tid < 32) {
            memv = mem_s[tid];
            float wpv = wp_s[tid], xbv = xb_s[tid];
            float upv = up_s[tid], udv = ud_s[tid];
            unsigned sb = (memv - 1.0f > 0.f) ? 1u : 0u;
            spk = (float)sb;
            unsigned ux = __float_as_uint(xbv);
            unsigned x16 = (ux + 0x7FFFu + ((ux >> 16) & 1u)) >> 16;  // bf16 rne
            g_rec[((size_t)t * Bn + b) * Nn + o0 + tid] =
                make_float2(spk * (1.0f + wpv), __uint_as_float((x16 << 16) | sb));
            spks[tid] = spk;
            potg[tid] = spk * fmaxf(upv, 0.f);
            depg[tid] = fmaxf(udv, 0.f);
            wp_s[tid] = 0.85f * wpv + spk * p_s[tid] * (1.0f + pd_s[tid] * wpv);
            xb_s[tid] = 0.95f * xbv + 0.05f * spk;
            up_s[tid] = 0.95f * upv + 0.05f * memv;
            ud_s[tid] = 0.95f * udv + 0.05f * memv;
        }
        __syncthreads();
        // ---- pre-barrier: stage delay>=2 bins (already final) ----
        {
            int dk[4] = {d0, d1, d2, d3};
#pragma unroll
            for (int k = 0; k < 4; k++) {
                if (dk[k] >= 2) {
                    size_t off = ((size_t)((t - dk[k]) & 63) * Bn + b) * Nn + tid;
                    gbuf[(k << 9) + tid] = __ldcg(&g_rec[off]);
                }
            }
        }
        // ---- readout partial (warp 1, overlaps barrier wait) ----
        if (wrp == 1) {
            int oo = lane;
            float acc = 0.f;
#pragma unroll
            for (int n = 0; n < 32; n++)
                acc = fmaf(spks[n], wouts[n * 32 + oo], acc);
            g_h2p[((size_t)cta * Tn + t) * NOn + oo] = acc;
        }
        // ---- per-batch grid barrier ----
        if (tid == 0) {
            __threadfence();
            atomicAdd(&g_bar[b * 32], 1u);
            unsigned tgt = 16u * (unsigned)(t + 1);
            while (*vb < tgt) __nanosleep(64);
            __threadfence();
        }
        __syncthreads();
        // ---- post-barrier: stage delay==1 bins ----
        {
            int dk[4] = {d0, d1, d2, d3};
#pragma unroll
            for (int k = 0; k < 4; k++) {
                if (dk[k] < 2) {
                    size_t off = ((size_t)((t - dk[k]) & 63) * Bn + b) * Nn + tid;
                    gbuf[(k << 9) + tid] = __ldcg(&g_rec[off]);
                }
            }
        }
        __syncthreads();
        // ---- Phase B: fused syn reduction + w_stdp update (regs + smem only) ----
#pragma unroll
        for (int pass = 0; pass < 2; pass++) {
            int ol = wrp * 2 + pass;
            float* wso = ws + ol * Nn;
            unsigned dpk = pass ? dp1 : dp0;
            float pot = potg[ol], dep = depg[ol];
            float acc = 0.f;
#pragma unroll
            for (int i = 0; i < 16; i++) {
                int e = lane + (i << 5);
                int dd = (dpk >> (2 * i)) & 3;
                float2 g = gbuf[(dd << 9) + e];           // {synp, enc}
                unsigned u = __float_as_uint(g.y);
                float xb   = __uint_as_float(u & 0xFFFF0000u);
                float outv = (float)(u & 1u);
                unsigned a = aar[pass * 16 + i];
                float ap = __uint_as_float(a << 16);
                float ad = __uint_as_float(a & 0xFFFF0000u);
                bool need = (u & 1u) || (pot != 0.f && xb != 0.f);
                float wsv = 0.f;
                if (need) wsv = wso[e];
                acc = fmaf(g.x * wvr[pass * 16 + i], wsv, acc);
                float dw = fmaf(xb * ap, pot, -(outv * ad * dep));
                if (need)
                    wso[e] = fminf(fmaxf(wsv + dw, 0.f), 2.f);
            }
#pragma unroll
            for (int off = 16; off; off >>= 1)
                acc += __shfl_xor_sync(0xFFFFFFFFu, acc, off);
            if (lane == 0) syn_s[ol] = acc;
        }
        __syncthreads();
        // ---- Phase C: membrane integration ----
        if (tid < 32) {
            float inpv = g_inp[((size_t)b * Tn + t) * Nn + o0 + tid];
            mem_s[tid] = 0.9f * memv + inpv + syn_s[tid] - spk;
        }
    }
}

// ---------------- readout: fixed-order 16-way sum + leaky scan ---------------
__global__ void k_scan(float* __restrict__ out) {
    int tid = threadIdx.x;               // 256 = B*NO
    int b = tid >> 5, oo = tid & 31;
    float o = 0.f;
    for (int t = 0; t < Tn; t++) {
        float s = 0.f;
#pragma unroll
        for (int ob = 0; ob < 16; ob++)
            s += g_h2p[((size_t)(b * 16 + ob) * Tn + t) * NOn + oo];
        o = 0.9f * o + s;
        out[((size_t)b * Tn + t) * NOn + oo] = o;
    }
}

// ---------------- launch -----------------------------------------------------
extern "C" void kernel_launch(void* const* d_in, const int* in_sizes, int n_in,
                              void* d_out, int out_size) {
    const float* inputs  = (const float*)d_in[0];
    const float* w       = (const float*)d_in[1];
    const float* w_in    = (const float*)d_in[2];
    const float* w_out   = (const float*)d_in[3];
    const float* dmap    = (const float*)d_in[4];
    const int*   delays  = (const int*)d_in[5];
    const float* w_signs = (const float*)d_in[6];
    const float* p       = (const float*)d_in[7];
    float* out = (float*)d_out;

    const int smem_bytes = OB * Nn * 4 + Dn * Nn * 8 + 32 * 32 * 4 + 2048; // ~86KB
    cudaFuncSetAttribute(k_step, cudaFuncAttributeMaxDynamicSharedMemorySize,
                         smem_bytes);

    k_pack<<<256, 256>>>(w, w_signs, (const float*)d_in[8], (const float*)d_in[9], dmap);
    k_inp<<<64, 256>>>(inputs, w_in);
    k_step<<<NBLK, NTHR, smem_bytes>>>(delays, p, w_out);
    k_scan<<<1, Bn * NOn>>>(out);
}

// round 13
// speedup vs baseline: 1.0450x; 1.0450x over previous
#include <cuda_runtime.h>

#define Bn   8
#define Tn   64
#define NIn  256
#define Nn   512
#define NOn  32
#define Dn   4
#define NBLK 128
#define NTHR 512
#define OB   32

// ---------------- global scratch (static __device__, allocation-free) --------
__device__ float          g_inp[Bn * Tn * Nn];        // input projection (b,t,n)
__device__ float2         g_rec[Tn * Bn * Nn];        // {synp, bf16(xb)|spikebit}
__device__ float2         g_pk[(size_t)Nn * Nn];      // per-(o,e): {wv, bf16x2(A_p,A_d)}
__device__ unsigned char  g_di[(size_t)Nn * Nn];      // per-(o,e): delay bin
__device__ float          g_h2p[NBLK * Tn * NOn];     // per-CTA readout partials
__device__ unsigned       g_bar[Bn * 32];             // per-batch barrier counters

// ---------------- K0: reset barriers, zero ring, build packed matrix ---------
__global__ void k_pack(const float* __restrict__ w,
                       const float* __restrict__ wsg,
                       const float* __restrict__ Ap,
                       const float* __restrict__ Ad,
                       const float* __restrict__ dmap) {
    if (blockIdx.x == 0 && threadIdx.x < Bn * 32) g_bar[threadIdx.x] = 0u;

    // zero the recording ring (replay determinism + (t-d)<0 wrap reads)
    {
        const int nf4 = Tn * Bn * Nn / 2;          // float4 count (float2 ring)
        float4 z = make_float4(0.f, 0.f, 0.f, 0.f);
        for (int i = blockIdx.x * blockDim.x + threadIdx.x; i < nf4;
             i += gridDim.x * blockDim.x)
            ((float4*)g_rec)[i] = z;
    }

    // 32x32 tile transpose: read (e,o)-major coalesced, write (o,e)-major coalesced
    __shared__ float         swv[32][33];
    __shared__ unsigned      sa[32][33];
    __shared__ unsigned char sdi[32][33];

    int tx = threadIdx.x & 31, ty = threadIdx.x >> 5;     // 32 x 8
    int te = (blockIdx.x & 15) << 5;
    int to = (blockIdx.x >> 4) << 5;

    for (int j = 0; j < 4; j++) {
        int e = te + ty + 8 * j, o = to + tx;
        size_t eo = (size_t)e * Nn + o;
        float wv = wsg[e] * fabsf(w[eo]);
        unsigned ua = __float_as_uint(Ap[eo]);
        unsigned ub = __float_as_uint(Ad[eo]);
        unsigned ap = (ua + 0x7FFFu + ((ua >> 16) & 1u)) >> 16;   // bf16 rne
        unsigned ad = (ub + 0x7FFFu + ((ub >> 16) & 1u)) >> 16;
        int d = 0;
        for (int dd = 0; dd < Dn; dd++)
            if (dmap[((size_t)dd * Nn + e) * Nn + o] > 0.5f) d = dd;
        swv[ty + 8 * j][tx] = wv;
        sa[ty + 8 * j][tx]  = ap | (ad << 16);
        sdi[ty + 8 * j][tx] = (unsigned char)d;
    }
    __syncthreads();
    for (int j = 0; j < 4; j++) {
        int o = to + ty + 8 * j, e = te + tx;
        g_pk[(size_t)o * Nn + e] =
            make_float2(swv[tx][ty + 8 * j], __uint_as_float(sa[tx][ty + 8 * j]));
        g_di[(size_t)o * Nn + e] = sdi[tx][ty + 8 * j];
    }
}

// ---------------- K_in: inp = einsum('btc,cn->btn', inputs, w_in) ------------
__global__ void k_inp(const float* __restrict__ x, const float* __restrict__ win) {
    __shared__ float xs[8][NIn];
    int bt0 = blockIdx.x * 8;
    int tid = threadIdx.x;                    // 256
    for (int i = tid; i < 8 * NIn; i += 256) {
        int r = i >> 8, c = i & 255;
        xs[r][c] = x[(size_t)(bt0 + r) * NIn + c];
    }
    __syncthreads();
    for (int half = 0; half < 2; half++) {
        int n = tid + half * 256;
        float acc[8] = {0.f, 0.f, 0.f, 0.f, 0.f, 0.f, 0.f, 0.f};
        for (int c = 0; c < NIn; c++) {
            float wv = win[(size_t)c * Nn + n];
#pragma unroll
            for (int r = 0; r < 8; r++) acc[r] = fmaf(xs[r][c], wv, acc[r]);
        }
#pragma unroll
        for (int r = 0; r < 8; r++) g_inp[(size_t)(bt0 + r) * Nn + n] = acc[r];
    }
}

// ---------------- K1: persistent stepping kernel -----------------------------
// CTA = (batch b, 32 output neurons). Synapse matrix in REGISTERS (persistent,
// 1 CTA/SM); w_stdp slab in smem; grid barrier per batch (16 CTAs).
__global__ void __launch_bounds__(NTHR, 1)
k_step(const int* __restrict__ delays, const float* __restrict__ p,
       const float* __restrict__ wout) {
    extern __shared__ char smem[];
    float*  ws    = (float*)smem;                                  // [OB][Nn] 64KB
    float2* gbuf  = (float2*)(smem + OB * Nn * 4);                 // [Dn][Nn] 16KB
    float*  wouts = (float*)(smem + OB * Nn * 4 + Dn * Nn * 8);    // [32][32] 4KB
    float*  aux   = wouts + 32 * 32;
    float* mem_s = aux +   0;  float* wp_s  = aux +  32;
    float* xb_s  = aux +  64;  float* up_s  = aux +  96;
    float* ud_s  = aux + 128;  float* potg  = aux + 160;
    float* depg  = aux + 192;  float* syn_s = aux + 224;
    float* p_s   = aux + 256;  float* pd_s  = aux + 288;
    float* spks  = aux + 320;
    int*   dly   = (int*)(aux + 352);

    const int tid = threadIdx.x;
    const int cta = blockIdx.x;
    const int b   = cta >> 4;
    const int o0  = (cta & 15) << 5;
    const int lane = tid & 31, wrp = tid >> 5;

    // ---- one-time: load this thread's 32 synapses into registers ----
    float    wvr[32];
    unsigned aar[32];
    unsigned dp0 = 0u, dp1 = 0u;
#pragma unroll
    for (int i = 0; i < 16; i++) {
        int e = lane + (i << 5);
        size_t r0 = (size_t)(o0 + wrp * 2 + 0) * Nn + e;
        size_t r1 = (size_t)(o0 + wrp * 2 + 1) * Nn + e;
        float2 m0 = __ldg(&g_pk[r0]);
        float2 m1 = __ldg(&g_pk[r1]);
        wvr[i]      = m0.x;  aar[i]      = __float_as_uint(m0.y);
        wvr[16 + i] = m1.x;  aar[16 + i] = __float_as_uint(m1.y);
        dp0 |= ((unsigned)__ldg(&g_di[r0]) & 3u) << (2 * i);
        dp1 |= ((unsigned)__ldg(&g_di[r1]) & 3u) << (2 * i);
    }

    for (int i = tid; i < OB * Nn; i += NTHR) ws[i] = 1.0f;
    for (int i = tid; i < 32 * 32; i += NTHR)
        wouts[i] = wout[(size_t)(o0 + (i >> 5)) * NOn + (i & 31)];
    if (tid < 32) {
        mem_s[tid] = 0.f; wp_s[tid] = 0.f; xb_s[tid] = 0.f;
        up_s[tid] = 0.f;  ud_s[tid] = 0.f;
        float pv = p[o0 + tid];
        p_s[tid] = pv; pd_s[tid] = (pv < 0.f) ? 1.f : 0.f;
    }
    if (tid < 4) dly[tid] = delays[tid];
    __syncthreads();
    const int d0 = dly[0], d1 = dly[1], d2 = dly[2], d3 = dly[3];

    volatile unsigned* vb = &g_bar[b * 32];
    float memv = 0.f, spk = 0.f;

    for (int t = 0; t < Tn; t++) {
        // ---- Phase A: spikes, recording, fast state (pre-update semantics) ----
        if (tid < 32) {
            memv = mem_s[tid];
            float wpv = wp_s[tid], xbv = xb_s[tid];
            float upv = up_s[tid], udv = ud_s[tid];
            unsigned sb = (memv - 1.0f > 0.f) ? 1u : 0u;
            spk = (float)sb;
            unsigned ux = __float_as_uint(xbv);
            unsigned x16 = (ux + 0x7FFFu + ((ux >> 16) & 1u)) >> 16;  // bf16 rne
            g_rec[((size_t)t * Bn + b) * Nn + o0 + tid] =
                make_float2(spk * (1.0f + wpv), __uint_as_float((x16 << 16) | sb));
            spks[tid] = spk;
            potg[tid] = spk * fmaxf(upv, 0.f);
            depg[tid] = fmaxf(udv, 0.f);
            wp_s[tid] = 0.85f * wpv + spk * p_s[tid] * (1.0f + pd_s[tid] * wpv);
            xb_s[tid] = 0.95f * xbv + 0.05f * spk;
            up_s[tid] = 0.95f * upv + 0.05f * memv;
            ud_s[tid] = 0.95f * udv + 0.05f * memv;
        }
        __syncthreads();
        // ---- pre-barrier: stage delay>=2 bins (already final) ----
        {
            int dk[4] = {d0, d1, d2, d3};
#pragma unroll
            for (int k = 0; k < 4; k++) {
                if (dk[k] >= 2) {
                    size_t off = ((size_t)((t - dk[k]) & 63) * Bn + b) * Nn + tid;
                    gbuf[(k << 9) + tid] = __ldcg(&g_rec[off]);
                }
            }
        }
        // ---- readout partial (warp 1, overlaps barrier wait) ----
        if (wrp == 1) {
            int oo = lane;
            float acc = 0.f;
#pragma unroll
            for (int n = 0; n < 32; n++)
                acc = fmaf(spks[n], wouts[n * 32 + oo], acc);
            g_h2p[((size_t)cta * Tn + t) * NOn + oo] = acc;
        }
        // ---- per-batch grid barrier ----
        if (tid == 0) {
            __threadfence();
            atomicAdd(&g_bar[b * 32], 1u);
            unsigned tgt = 16u * (unsigned)(t + 1);
            while (*vb < tgt) __nanosleep(64);
            __threadfence();
        }
        __syncthreads();
        // ---- post-barrier: stage delay==1 bins ----
        {
            int dk[4] = {d0, d1, d2, d3};
#pragma unroll
            for (int k = 0; k < 4; k++) {
                if (dk[k] < 2) {
                    size_t off = ((size_t)((t - dk[k]) & 63) * Bn + b) * Nn + tid;
                    gbuf[(k << 9) + tid] = __ldcg(&g_rec[off]);
                }
            }
        }
        __syncthreads();
        // ---- Phase B: fused syn reduction + w_stdp update (regs + smem only) ----
#pragma unroll
        for (int pass = 0; pass < 2; pass++) {
            int ol = wrp * 2 + pass;
            float* wso = ws + ol * Nn;
            unsigned dpk = pass ? dp1 : dp0;
            float pot = potg[ol], dep = depg[ol];
            float acc = 0.f;
#pragma unroll
            for (int i = 0; i < 16; i++) {
                int e = lane + (i << 5);
                int dd = (dpk >> (2 * i)) & 3;
                float2 g = gbuf[(dd << 9) + e];           // {synp, enc}
                unsigned u = __float_as_uint(g.y);
                float xb   = __uint_as_float(u & 0xFFFF0000u);
                float outv = (float)(u & 1u);
                unsigned a = aar[pass * 16 + i];
                float ap = __uint_as_float(a << 16);
                float ad = __uint_as_float(a & 0xFFFF0000u);
                bool need = (u & 1u) || (pot != 0.f && xb != 0.f);
                float wsv = 0.f;
                if (need) wsv = wso[e];
                acc = fmaf(g.x * wvr[pass * 16 + i], wsv, acc);
                float dw = fmaf(xb * ap, pot, -(outv * ad * dep));
                if (need)
                    wso[e] = fminf(fmaxf(wsv + dw, 0.f), 2.f);
            }
#pragma unroll
            for (int off = 16; off; off >>= 1)
                acc += __shfl_xor_sync(0xFFFFFFFFu, acc, off);
            if (lane == 0) syn_s[ol] = acc;
        }
        __syncthreads();
        // ---- Phase C: membrane integration ----
        if (tid < 32) {
            float inpv = g_inp[((size_t)b * Tn + t) * Nn + o0 + tid];
            mem_s[tid] = 0.9f * memv + inpv + syn_s[tid] - spk;
        }
    }
}

// ---------------- readout: fixed-order 16-way sum + leaky scan ---------------
__global__ void k_scan(float* __restrict__ out) {
    int tid = threadIdx.x;               // 256 = B*NO
    int b = tid >> 5, oo = tid & 31;
    float o = 0.f;
    for (int t = 0; t < Tn; t++) {
        float s = 0.f;
#pragma unroll
        for (int ob = 0; ob < 16; ob++)
            s += g_h2p[((size_t)(b * 16 + ob) * Tn + t) * NOn + oo];
        o = 0.9f * o + s;
        out[((size_t)b * Tn + t) * NOn + oo] = o;
    }
}

// ---------------- launch -----------------------------------------------------
extern "C" void kernel_launch(void* const* d_in, const int* in_sizes, int n_in,
                              void* d_out, int out_size) {
    const float* inputs  = (const float*)d_in[0];
    const float* w       = (const float*)d_in[1];
    const float* w_in    = (const float*)d_in[2];
    const float* w_out   = (const float*)d_in[3];
    const float* dmap    = (const float*)d_in[4];
    const int*   delays  = (const int*)d_in[5];
    const float* w_signs = (const float*)d_in[6];
    const float* p       = (const float*)d_in[7];
    float* out = (float*)d_out;

    const int smem_bytes = OB * Nn * 4 + Dn * Nn * 8 + 32 * 32 * 4 + 2048; // ~86KB
    cudaFuncSetAttribute(k_step, cudaFuncAttributeMaxDynamicSharedMemorySize,
                         smem_bytes);

    k_pack<<<256, 256>>>(w, w_signs, (const float*)d_in[8], (const float*)d_in[9], dmap);
    k_inp<<<64, 256>>>(inputs, w_in);
    k_step<<<NBLK, NTHR, smem_bytes>>>(delays, p, w_out);
    k_scan<<<1, Bn * NOn>>>(out);
}

// round 14
// speedup vs baseline: 1.0661x; 1.0202x over previous
#include <cuda_runtime.h>

#define Bn   8
#define Tn   64
#define NIn  256
#define Nn   512
#define NOn  32
#define Dn   4
#define NBLK 128
#define NTHR 512
#define OB   32

// ---------------- global scratch (static __device__, allocation-free) --------
__device__ float          g_inp[Bn * Tn * Nn];        // input projection (b,t,n)
__device__ float2         g_rec[Tn * Bn * Nn];        // {synp, bf16(xb)|spikebit}
__device__ float2         g_pk[(size_t)Nn * Nn];      // per-(o,e): {wv, bf16x2(A_p,A_d)}
__device__ unsigned char  g_di[(size_t)Nn * Nn];      // per-(o,e): delay bin
__device__ float          g_h2p[NBLK * Tn * NOn];     // per-CTA readout partials
__device__ unsigned       g_ep[NBLK];                 // per-CTA completed-PhaseA epoch

// ---------------- K0: reset epochs, zero ring, build packed matrix -----------
__global__ void k_pack(const float* __restrict__ w,
                       const float* __restrict__ wsg,
                       const float* __restrict__ Ap,
                       const float* __restrict__ Ad,
                       const float* __restrict__ dmap) {
    if (blockIdx.x == 0 && threadIdx.x < NBLK) g_ep[threadIdx.x] = 0u;

    // zero the recording ring (replay determinism + (t-d)<0 wrap reads)
    {
        const int nf4 = Tn * Bn * Nn / 2;          // float4 count (float2 ring)
        float4 z = make_float4(0.f, 0.f, 0.f, 0.f);
        for (int i = blockIdx.x * blockDim.x + threadIdx.x; i < nf4;
             i += gridDim.x * blockDim.x)
            ((float4*)g_rec)[i] = z;
    }

    // 32x32 tile transpose: read (e,o)-major coalesced, write (o,e)-major coalesced
    __shared__ float         swv[32][33];
    __shared__ unsigned      sa[32][33];
    __shared__ unsigned char sdi[32][33];

    int tx = threadIdx.x & 31, ty = threadIdx.x >> 5;     // 32 x 8
    int te = (blockIdx.x & 15) << 5;
    int to = (blockIdx.x >> 4) << 5;

    for (int j = 0; j < 4; j++) {
        int e = te + ty + 8 * j, o = to + tx;
        size_t eo = (size_t)e * Nn + o;
        float wv = wsg[e] * fabsf(w[eo]);
        unsigned ua = __float_as_uint(Ap[eo]);
        unsigned ub = __float_as_uint(Ad[eo]);
        unsigned ap = (ua + 0x7FFFu + ((ua >> 16) & 1u)) >> 16;   // bf16 rne
        unsigned ad = (ub + 0x7FFFu + ((ub >> 16) & 1u)) >> 16;
        int d = 0;
        for (int dd = 0; dd < Dn; dd++)
            if (dmap[((size_t)dd * Nn + e) * Nn + o] > 0.5f) d = dd;
        swv[ty + 8 * j][tx] = wv;
        sa[ty + 8 * j][tx]  = ap | (ad << 16);
        sdi[ty + 8 * j][tx] = (unsigned char)d;
    }
    __syncthreads();
    for (int j = 0; j < 4; j++) {
        int o = to + ty + 8 * j, e = te + tx;
        g_pk[(size_t)o * Nn + e] =
            make_float2(swv[tx][ty + 8 * j], __uint_as_float(sa[tx][ty + 8 * j]));
        g_di[(size_t)o * Nn + e] = sdi[tx][ty + 8 * j];
    }
}

// ---------------- K_in: inp = einsum('btc,cn->btn', inputs, w_in) ------------
__global__ void k_inp(const float* __restrict__ x, const float* __restrict__ win) {
    __shared__ float xs[8][NIn];
    int bt0 = blockIdx.x * 8;
    int tid = threadIdx.x;                    // 256
    for (int i = tid; i < 8 * NIn; i += 256) {
        int r = i >> 8, c = i & 255;
        xs[r][c] = x[(size_t)(bt0 + r) * NIn + c];
    }
    __syncthreads();
    for (int half = 0; half < 2; half++) {
        int n = tid + half * 256;
        float acc[8] = {0.f, 0.f, 0.f, 0.f, 0.f, 0.f, 0.f, 0.f};
        for (int c = 0; c < NIn; c++) {
            float wv = win[(size_t)c * Nn + n];
#pragma unroll
            for (int r = 0; r < 8; r++) acc[r] = fmaf(xs[r][c], wv, acc[r]);
        }
#pragma unroll
        for (int r = 0; r < 8; r++) g_inp[(size_t)(bt0 + r) * Nn + n] = acc[r];
    }
}

// ---------------- K1: persistent stepping kernel -----------------------------
// CTA = (batch b, 32 output neurons). Matrix in registers; w_stdp slab in smem.
// Relaxed dependency barrier: step t only requires Phase A of step t-1 from the
// 16 CTAs of the same batch -> per-CTA epoch flags give a full step of slack.
__global__ void __launch_bounds__(NTHR, 1)
k_step(const int* __restrict__ delays, const float* __restrict__ p,
       const float* __restrict__ wout) {
    extern __shared__ char smem[];
    float*  ws    = (float*)smem;                                  // [OB][Nn] 64KB
    float2* gbuf  = (float2*)(smem + OB * Nn * 4);                 // [Dn][Nn] 16KB
    float*  wouts = (float*)(smem + OB * Nn * 4 + Dn * Nn * 8);    // [32][32] 4KB
    float*  aux   = wouts + 32 * 32;
    float* mem_s = aux +   0;  float* wp_s  = aux +  32;
    float* xb_s  = aux +  64;  float* up_s  = aux +  96;
    float* ud_s  = aux + 128;  float* potg  = aux + 160;
    float* depg  = aux + 192;  float* syn_s = aux + 224;
    float* p_s   = aux + 256;  float* pd_s  = aux + 288;
    float* spks  = aux + 320;
    int*   dly   = (int*)(aux + 352);

    const int tid = threadIdx.x;
    const int cta = blockIdx.x;
    const int b   = cta >> 4;
    const int o0  = (cta & 15) << 5;
    const int lane = tid & 31, wrp = tid >> 5;

    // ---- one-time: load this thread's 32 synapses into registers ----
    float    wvr[32];
    unsigned aar[32];
    unsigned dp0 = 0u, dp1 = 0u;
#pragma unroll
    for (int i = 0; i < 16; i++) {
        int e = lane + (i << 5);
        size_t r0 = (size_t)(o0 + wrp * 2 + 0) * Nn + e;
        size_t r1 = (size_t)(o0 + wrp * 2 + 1) * Nn + e;
        float2 m0 = __ldg(&g_pk[r0]);
        float2 m1 = __ldg(&g_pk[r1]);
        wvr[i]      = m0.x;  aar[i]      = __float_as_uint(m0.y);
        wvr[16 + i] = m1.x;  aar[16 + i] = __float_as_uint(m1.y);
        dp0 |= ((unsigned)__ldg(&g_di[r0]) & 3u) << (2 * i);
        dp1 |= ((unsigned)__ldg(&g_di[r1]) & 3u) << (2 * i);
    }

    for (int i = tid; i < OB * Nn; i += NTHR) ws[i] = 1.0f;
    for (int i = tid; i < 32 * 32; i += NTHR)
        wouts[i] = wout[(size_t)(o0 + (i >> 5)) * NOn + (i & 31)];
    if (tid < 32) {
        mem_s[tid] = 0.f; wp_s[tid] = 0.f; xb_s[tid] = 0.f;
        up_s[tid] = 0.f;  ud_s[tid] = 0.f;
        float pv = p[o0 + tid];
        p_s[tid] = pv; pd_s[tid] = (pv < 0.f) ? 1.f : 0.f;
    }
    if (tid < 4) dly[tid] = delays[tid];
    __syncthreads();
    const int d0 = dly[0], d1 = dly[1], d2 = dly[2], d3 = dly[3];

    float memv = 0.f, spk = 0.f;

    for (int t = 0; t < Tn; t++) {
        // ---- Phase A: spikes, recording, fast state (pre-update semantics) ----
        if (tid < 32) {
            memv = mem_s[tid];
            float wpv = wp_s[tid], xbv = xb_s[tid];
            float upv = up_s[tid], udv = ud_s[tid];
            unsigned sb = (memv - 1.0f > 0.f) ? 1u : 0u;
            spk = (float)sb;
            unsigned ux = __float_as_uint(xbv);
            unsigned x16 = (ux + 0x7FFFu + ((ux >> 16) & 1u)) >> 16;  // bf16 rne
            g_rec[((size_t)t * Bn + b) * Nn + o0 + tid] =
                make_float2(spk * (1.0f + wpv), __uint_as_float((x16 << 16) | sb));
            spks[tid] = spk;
            potg[tid] = spk * fmaxf(upv, 0.f);
            depg[tid] = fmaxf(udv, 0.f);
            wp_s[tid] = 0.85f * wpv + spk * p_s[tid] * (1.0f + pd_s[tid] * wpv);
            xb_s[tid] = 0.95f * xbv + 0.05f * spk;
            up_s[tid] = 0.95f * upv + 0.05f * memv;
            ud_s[tid] = 0.95f * udv + 0.05f * memv;
        }
        __syncthreads();     // rec(t) written; spks/potg/depg visible
        // ---- publish epoch t+1, then relaxed wait: all peers at epoch >= t ----
        if (tid == 0) {
            __threadfence();                       // rec(t) -> L2 before flag
            atomicExch(&g_ep[cta], (unsigned)(t + 1));
        }
        // readout partial (warp 1) overlaps the publish/wait
        if (wrp == 1) {
            int oo = lane;
            float acc = 0.f;
#pragma unroll
            for (int n = 0; n < 32; n++)
                acc = fmaf(spks[n], wouts[n * 32 + oo], acc);
            g_h2p[((size_t)cta * Tn + t) * NOn + oo] = acc;
        }
        if (tid < 16) {
            volatile unsigned* f = (volatile unsigned*)&g_ep[(b << 4) + tid];
            while (*f < (unsigned)t) __nanosleep(32);
            __threadfence();                       // acquire before ring reads
        }
        __syncthreads();
        // ---- stage all 4 delay bins (all data <= t-1, covered by the wait) ----
        {
            int dk[4] = {d0, d1, d2, d3};
#pragma unroll
            for (int k = 0; k < 4; k++) {
                size_t off = ((size_t)((t - dk[k]) & 63) * Bn + b) * Nn + tid;
                gbuf[(k << 9) + tid] = __ldcg(&g_rec[off]);
            }
        }
        __syncthreads();
        // ---- Phase B: fused syn reduction + w_stdp update (regs + smem only) ----
#pragma unroll
        for (int pass = 0; pass < 2; pass++) {
            int ol = wrp * 2 + pass;
            float* wso = ws + ol * Nn;
            unsigned dpk = pass ? dp1 : dp0;
            float pot = potg[ol], dep = depg[ol];
            float acc = 0.f;
#pragma unroll
            for (int i = 0; i < 16; i++) {
                int e = lane + (i << 5);
                int dd = (dpk >> (2 * i)) & 3;
                float2 g = gbuf[(dd << 9) + e];           // {synp, enc}
                unsigned u = __float_as_uint(g.y);
                float xb   = __uint_as_float(u & 0xFFFF0000u);
                float outv = (float)(u & 1u);
                unsigned a = aar[pass * 16 + i];
                float ap = __uint_as_float(a << 16);
                float ad = __uint_as_float(a & 0xFFFF0000u);
                bool need = (u & 1u) || (pot != 0.f && xb != 0.f);
                float wsv = 0.f;
                if (need) wsv = wso[e];
                acc = fmaf(g.x * wvr[pass * 16 + i], wsv, acc);
                float dw = fmaf(xb * ap, pot, -(outv * ad * dep));
                if (need)
                    wso[e] = fminf(fmaxf(wsv + dw, 0.f), 2.f);
            }
#pragma unroll
            for (int off = 16; off; off >>= 1)
                acc += __shfl_xor_sync(0xFFFFFFFFu, acc, off);
            if (lane == 0) syn_s[ol] = acc;
        }
        __syncthreads();
        // ---- Phase C: membrane integration (same threads as Phase A) ----
        if (tid < 32) {
            float inpv = g_inp[((size_t)b * Tn + t) * Nn + o0 + tid];
            mem_s[tid] = 0.9f * memv + inpv + syn_s[tid] - spk;
        }
        // no sync needed: mem_s[tid] written & read by the same thread
    }
}

// ---------------- readout: per-batch parallel 16-way sum + smem scan ---------
__global__ void k_scan(float* __restrict__ out) {
    __shared__ float hs[Tn][NOn + 1];
    int b = blockIdx.x;                     // 8 blocks
    int tid = threadIdx.x;                  // 512
    for (int idx = tid; idx < Tn * NOn; idx += 512) {
        int t = idx >> 5, oo = idx & 31;
        float s = 0.f;
#pragma unroll
        for (int ob = 0; ob < 16; ob++)
            s += g_h2p[((size_t)(b * 16 + ob) * Tn + t) * NOn + oo];
        hs[t][oo] = s;
    }
    __syncthreads();
    if (tid < NOn) {
        float o = 0.f;
        for (int t = 0; t < Tn; t++) {
            o = 0.9f * o + hs[t][tid];
            out[((size_t)b * Tn + t) * NOn + tid] = o;
        }
    }
}

// ---------------- launch -----------------------------------------------------
extern "C" void kernel_launch(void* const* d_in, const int* in_sizes, int n_in,
                              void* d_out, int out_size) {
    const float* inputs  = (const float*)d_in[0];
    const float* w       = (const float*)d_in[1];
    const float* w_in    = (const float*)d_in[2];
    const float* w_out   = (const float*)d_in[3];
    const float* dmap    = (const float*)d_in[4];
    const int*   delays  = (const int*)d_in[5];
    const float* w_signs = (const float*)d_in[6];
    const float* p       = (const float*)d_in[7];
    float* out = (float*)d_out;

    const int smem_bytes = OB * Nn * 4 + Dn * Nn * 8 + 32 * 32 * 4 + 2048; // ~86KB
    cudaFuncSetAttribute(k_step, cudaFuncAttributeMaxDynamicSharedMemorySize,
                         smem_bytes);

    k_pack<<<256, 256>>>(w, w_signs, (const float*)d_in[8], (const float*)d_in[9], dmap);
    k_inp<<<64, 256>>>(inputs, w_in);
    k_step<<<NBLK, NTHR, smem_bytes>>>(delays, p, w_out);
    k_scan<<<Bn, 512>>>(out);
}

// round 15
// speedup vs baseline: 1.4503x; 1.3604x over previous
#include <cuda_runtime.h>

#define Bn   8
#define Tn   64
#define NIn  256
#define Nn   512
#define NOn  32
#define Dn   4
#define NBLK 128
#define NTHR 512
#define OB   32

// ---------------- global scratch (static __device__, allocation-free) --------
__device__ float          g_inp[Bn * Tn * Nn];        // input projection (b,t,n)
__device__ float2         g_rec[Tn * Bn * Nn];        // {synp, bf16(xb)|spikebit}
__device__ float2         g_pk[(size_t)Nn * Nn];      // per-(o,e): {wv, bf16x2(A_p,A_d)}
__device__ unsigned char  g_di[(size_t)Nn * Nn];      // per-(o,e): delay bin
__device__ float          g_h2p[NBLK * Tn * NOn];     // per-CTA readout partials
__device__ unsigned       g_ep[NBLK];                 // per-CTA completed-PhaseA epoch

// ---------------- K0: reset epochs, zero ring, build packed matrix -----------
__global__ void k_pack(const float* __restrict__ w,
                       const float* __restrict__ wsg,
                       const float* __restrict__ Ap,
                       const float* __restrict__ Ad,
                       const float* __restrict__ dmap) {
    if (blockIdx.x == 0 && threadIdx.x < NBLK) g_ep[threadIdx.x] = 0u;

    // zero the recording ring (replay determinism + (t-d)<0 wrap reads)
    {
        const int nf4 = Tn * Bn * Nn / 2;          // float4 count (float2 ring)
        float4 z = make_float4(0.f, 0.f, 0.f, 0.f);
        for (int i = blockIdx.x * blockDim.x + threadIdx.x; i < nf4;
             i += gridDim.x * blockDim.x)
            ((float4*)g_rec)[i] = z;
    }

    // 32x32 tile transpose: read (e,o)-major coalesced, write (o,e)-major coalesced
    __shared__ float         swv[32][33];
    __shared__ unsigned      sa[32][33];
    __shared__ unsigned char sdi[32][33];

    int tx = threadIdx.x & 31, ty = threadIdx.x >> 5;     // 32 x 8
    int te = (blockIdx.x & 15) << 5;
    int to = (blockIdx.x >> 4) << 5;

    for (int j = 0; j < 4; j++) {
        int e = te + ty + 8 * j, o = to + tx;
        size_t eo = (size_t)e * Nn + o;
        float wv = wsg[e] * fabsf(w[eo]);
        unsigned ua = __float_as_uint(Ap[eo]);
        unsigned ub = __float_as_uint(Ad[eo]);
        unsigned ap = (ua + 0x7FFFu + ((ua >> 16) & 1u)) >> 16;   // bf16 rne
        unsigned ad = (ub + 0x7FFFu + ((ub >> 16) & 1u)) >> 16;
        int d = 0;
        for (int dd = 0; dd < Dn; dd++)
            if (dmap[((size_t)dd * Nn + e) * Nn + o] > 0.5f) d = dd;
        swv[ty + 8 * j][tx] = wv;
        sa[ty + 8 * j][tx]  = ap | (ad << 16);
        sdi[ty + 8 * j][tx] = (unsigned char)d;
    }
    __syncthreads();
    for (int j = 0; j < 4; j++) {
        int o = to + ty + 8 * j, e = te + tx;
        g_pk[(size_t)o * Nn + e] =
            make_float2(swv[tx][ty + 8 * j], __uint_as_float(sa[tx][ty + 8 * j]));
        g_di[(size_t)o * Nn + e] = sdi[tx][ty + 8 * j];
    }
}

// ---------------- K_in: inp = einsum('btc,cn->btn', inputs, w_in) ------------
__global__ void k_inp(const float* __restrict__ x, const float* __restrict__ win) {
    __shared__ float xs[8][NIn];
    int bt0 = blockIdx.x * 8;
    int tid = threadIdx.x;                    // 256
    for (int i = tid; i < 8 * NIn; i += 256) {
        int r = i >> 8, c = i & 255;
        xs[r][c] = x[(size_t)(bt0 + r) * NIn + c];
    }
    __syncthreads();
    for (int half = 0; half < 2; half++) {
        int n = tid + half * 256;
        float acc[8] = {0.f, 0.f, 0.f, 0.f, 0.f, 0.f, 0.f, 0.f};
        for (int c = 0; c < NIn; c++) {
            float wv = win[(size_t)c * Nn + n];
#pragma unroll
            for (int r = 0; r < 8; r++) acc[r] = fmaf(xs[r][c], wv, acc[r]);
        }
#pragma unroll
        for (int r = 0; r < 8; r++) g_inp[(size_t)(bt0 + r) * Nn + n] = acc[r];
    }
}

// ---------------- K1: persistent stepping kernel -----------------------------
// CTA = (batch b, 32 output neurons). Matrix streamed from L1 (slab 128KB fits
// the 140KB L1 left by 88KB smem; __ldcg ring reads bypass L1 so it persists).
// Relaxed dependency barrier: per-CTA epoch flags, 1 full step of slack.
__global__ void __launch_bounds__(NTHR, 1)
k_step(const int* __restrict__ delays, const float* __restrict__ p,
       const float* __restrict__ wout) {
    extern __shared__ char smem[];
    float*  ws    = (float*)smem;                                  // [OB][Nn] 64KB
    float2* gbuf  = (float2*)(smem + OB * Nn * 4);                 // [Dn][Nn] 16KB
    float*  wouts = (float*)(smem + OB * Nn * 4 + Dn * Nn * 8);    // [32][32] 4KB
    float*  aux   = wouts + 32 * 32;
    float* mem_s = aux +   0;  float* wp_s  = aux +  32;
    float* xb_s  = aux +  64;  float* up_s  = aux +  96;
    float* ud_s  = aux + 128;  float* potg  = aux + 160;
    float* depg  = aux + 192;  float* syn_s = aux + 224;
    float* p_s   = aux + 256;  float* pd_s  = aux + 288;
    float* spks  = aux + 320;
    int*   dly   = (int*)(aux + 352);

    const int tid = threadIdx.x;
    const int cta = blockIdx.x;
    const int b   = cta >> 4;
    const int o0  = (cta & 15) << 5;
    const int lane = tid & 31, wrp = tid >> 5;

    // ---- one-time: delay bins for this thread's 32 synapses -> 2 registers ----
    unsigned dp0 = 0u, dp1 = 0u;
#pragma unroll
    for (int i = 0; i < 16; i++) {
        int e = lane + (i << 5);
        dp0 |= ((unsigned)__ldg(&g_di[(size_t)(o0 + wrp * 2 + 0) * Nn + e]) & 3u) << (2 * i);
        dp1 |= ((unsigned)__ldg(&g_di[(size_t)(o0 + wrp * 2 + 1) * Nn + e]) & 3u) << (2 * i);
    }

    for (int i = tid; i < OB * Nn; i += NTHR) ws[i] = 1.0f;
    for (int i = tid; i < 32 * 32; i += NTHR)
        wouts[i] = wout[(size_t)(o0 + (i >> 5)) * NOn + (i & 31)];
    if (tid < 32) {
        mem_s[tid] = 0.f; wp_s[tid] = 0.f; xb_s[tid] = 0.f;
        up_s[tid] = 0.f;  ud_s[tid] = 0.f;
        float pv = p[o0 + tid];
        p_s[tid] = pv; pd_s[tid] = (pv < 0.f) ? 1.f : 0.f;
    }
    if (tid < 4) dly[tid] = delays[tid];
    __syncthreads();
    const int d0 = dly[0], d1 = dly[1], d2 = dly[2], d3 = dly[3];
    const int dk[4] = {d0, d1, d2, d3};

    float memv = 0.f, spk = 0.f, inpv = 0.f;

    for (int t = 0; t < Tn; t++) {
        // ---- Phase A: spikes, recording, fast state (pre-update semantics) ----
        if (tid < 32) {
            inpv = g_inp[((size_t)b * Tn + t) * Nn + o0 + tid];   // prefetch for C
            memv = mem_s[tid];
            float wpv = wp_s[tid], xbv = xb_s[tid];
            float upv = up_s[tid], udv = ud_s[tid];
            unsigned sb = (memv - 1.0f > 0.f) ? 1u : 0u;
            spk = (float)sb;
            unsigned ux = __float_as_uint(xbv);
            unsigned x16 = (ux + 0x7FFFu + ((ux >> 16) & 1u)) >> 16;  // bf16 rne
            g_rec[((size_t)t * Bn + b) * Nn + o0 + tid] =
                make_float2(spk * (1.0f + wpv), __uint_as_float((x16 << 16) | sb));
            spks[tid] = spk;
            potg[tid] = spk * fmaxf(upv, 0.f);
            depg[tid] = fmaxf(udv, 0.f);
            wp_s[tid] = 0.85f * wpv + spk * p_s[tid] * (1.0f + pd_s[tid] * wpv);
            xb_s[tid] = 0.95f * xbv + 0.05f * spk;
            up_s[tid] = 0.95f * upv + 0.05f * memv;
            ud_s[tid] = 0.95f * udv + 0.05f * memv;
        }
        __syncthreads();     // rec(t) CTA-visible; spks/potg/depg visible
        // ---- publish epoch t+1 ASAP ----
        if (tid == 0) {
            __threadfence();                       // rec(t) -> L2 before flag
            atomicExch(&g_ep[cta], (unsigned)(t + 1));
        }
        // ---- stage delay>=2 bins (data <= t-2, covered by PREVIOUS wait) ----
#pragma unroll
        for (int k = 0; k < 4; k++) {
            if (dk[k] >= 2) {
                size_t off = ((size_t)((t - dk[k]) & 63) * Bn + b) * Nn + tid;
                gbuf[(k << 9) + tid] = __ldcg(&g_rec[off]);
            }
        }
        // ---- readout partial (warp 1) overlaps the wait ----
        if (wrp == 1) {
            int oo = lane;
            float acc = 0.f;
#pragma unroll
            for (int n = 0; n < 32; n++)
                acc = fmaf(spks[n], wouts[n * 32 + oo], acc);
            g_h2p[((size_t)cta * Tn + t) * NOn + oo] = acc;
        }
        // ---- relaxed wait: peers' Phase A of step t-1 done (flag >= t) ----
        if (tid < 16) {
            volatile unsigned* f = (volatile unsigned*)&g_ep[(b << 4) + tid];
            while (*f < (unsigned)t) __nanosleep(32);
            __threadfence();                       // acquire before ring reads
        }
        __syncthreads();
        // ---- stage delay==1 bins (short post-wait path) ----
#pragma unroll
        for (int k = 0; k < 4; k++) {
            if (dk[k] < 2) {
                size_t off = ((size_t)((t - dk[k]) & 63) * Bn + b) * Nn + tid;
                gbuf[(k << 9) + tid] = __ldcg(&g_rec[off]);
            }
        }
        __syncthreads();
        // ---- Phase B: fused syn reduction + w_stdp update (L1 matrix stream) ----
#pragma unroll
        for (int pass = 0; pass < 2; pass++) {
            int ol = wrp * 2 + pass;
            const float2* __restrict__ pko = g_pk + (size_t)(o0 + ol) * Nn;
            float* wso = ws + ol * Nn;
            unsigned dpk = pass ? dp1 : dp0;
            float pot = potg[ol], dep = depg[ol];
            float acc = 0.f;
#pragma unroll
            for (int i = 0; i < 16; i++) {
                int e = lane + (i << 5);
                float2 m = __ldg(&pko[e]);        // L1-resident after step 0
                int dd = (dpk >> (2 * i)) & 3;
                float2 g = gbuf[(dd << 9) + e];   // {synp, enc}
                unsigned u = __float_as_uint(g.y);
                float xb   = __uint_as_float(u & 0xFFFF0000u);
                unsigned a = __float_as_uint(m.y);
                float ap = __uint_as_float(a << 16);
                float ad = __uint_as_float(a & 0xFFFF0000u);
                bool presyn = (u & 1u) != 0u;
                bool need = presyn | ((pot != 0.f) & (xb != 0.f));
                float wsv = 0.f;
                if (need | (g.x != 0.f)) wsv = wso[e];
                acc = fmaf(g.x * m.x, wsv, acc);
                float depr = presyn ? ad * dep : 0.f;
                float dw = fmaf(xb * ap, pot, -depr);
                if (need)
                    wso[e] = fminf(fmaxf(wsv + dw, 0.f), 2.f);
            }
#pragma unroll
            for (int off = 16; off; off >>= 1)
                acc += __shfl_xor_sync(0xFFFFFFFFu, acc, off);
            if (lane == 0) syn_s[ol] = acc;
        }
        __syncthreads();
        // ---- Phase C: membrane integration (same threads as Phase A) ----
        if (tid < 32)
            mem_s[tid] = 0.9f * memv + inpv + syn_s[tid] - spk;
        // no sync needed: mem_s[tid] written & read by the same thread
    }
}

// ---------------- readout: per-batch parallel 16-way sum + smem scan ---------
__global__ void k_scan(float* __restrict__ out) {
    __shared__ float hs[Tn][NOn + 1];
    int b = blockIdx.x;                     // 8 blocks
    int tid = threadIdx.x;                  // 512
    for (int idx = tid; idx < Tn * NOn; idx += 512) {
        int t = idx >> 5, oo = idx & 31;
        float s = 0.f;
#pragma unroll
        for (int ob = 0; ob < 16; ob++)
            s += g_h2p[((size_t)(b * 16 + ob) * Tn + t) * NOn + oo];
        hs[t][oo] = s;
    }
    __syncthreads();
    if (tid < NOn) {
        float o = 0.f;
        for (int t = 0; t < Tn; t++) {
            o = 0.9f * o + hs[t][tid];
            out[((size_t)b * Tn + t) * NOn + tid] = o;
        }
    }
}

// ---------------- launch -----------------------------------------------------
extern "C" void kernel_launch(void* const* d_in, const int* in_sizes, int n_in,
                              void* d_out, int out_size) {
    const float* inputs  = (const float*)d_in[0];
    const float* w       = (const float*)d_in[1];
    const float* w_in    = (const float*)d_in[2];
    const float* w_out   = (const float*)d_in[3];
    const float* dmap    = (const float*)d_in[4];
    const int*   delays  = (const int*)d_in[5];
    const float* w_signs = (const float*)d_in[6];
    const float* p       = (const float*)d_in[7];
    float* out = (float*)d_out;

    const int smem_bytes = OB * Nn * 4 + Dn * Nn * 8 + 32 * 32 * 4 + 2048; // ~88KB
    cudaFuncSetAttribute(k_step, cudaFuncAttributeMaxDynamicSharedMemorySize,
                         smem_bytes);

    k_pack<<<256, 256>>>(w, w_signs, (const float*)d_in[8], (const float*)d_in[9], dmap);
    k_inp<<<64, 256>>>(inputs, w_in);
    k_step<<<NBLK, NTHR, smem_bytes>>>(delays, p, w_out);
    k_scan<<<Bn, 512>>>(out);
}